// round 1
// baseline (speedup 1.0000x reference)
#include <cuda_runtime.h>
#include <cuda_bf16.h>
#include <stdint.h>

// ---------------------------------------------------------------------------
// Quantized bottleneck: all convs are exact int8 GEMMs (weights in {-4..4},
// activations in [-128,127] after each BN/clip/relu). We run them on tensor
// cores via mma.sync.m16n8k32.s8 and replicate the float BN epilogue exactly
// (no FMA contraction, rintf = round-half-even like jnp.round).
// ---------------------------------------------------------------------------

#define NIMG   16
#define HW     784           // 28*28
#define NS     12544         // NIMG*HW
#define CIN    1024
#define CMID   256
#define COUT   1024

// scratch (device globals: allowed; no runtime allocation)
__device__ int8_t g_x8[NS * CIN];          // x packed NHWC int8  (12.8 MB)
__device__ int8_t g_w1[CMID * CIN];        // [co][ci]
__device__ int8_t g_w2[CMID * 2304];       // [co][kh][kw][ci]
__device__ int8_t g_w3[COUT * CMID];       // [co][ci]
__device__ int8_t g_y1[NS * CMID];         // NHWC int8
__device__ int8_t g_y2[NS * CMID];         // NHWC int8

#define DI __device__ __forceinline__

DI void mma8(int* d, const unsigned* a, const unsigned* b) {
    asm volatile(
        "mma.sync.aligned.m16n8k32.row.col.s32.s8.s8.s32 "
        "{%0,%1,%2,%3}, {%4,%5,%6,%7}, {%8,%9}, {%0,%1,%2,%3};\n"
        : "+r"(d[0]), "+r"(d[1]), "+r"(d[2]), "+r"(d[3])
        : "r"(a[0]), "r"(a[1]), "r"(a[2]), "r"(a[3]),
          "r"(b[0]), "r"(b[1]));
}

// BN: round((alpha*c + beta*2^(q+12)) * 2^-12), clip to [-128,127].
// Must match fp32 op-for-op: mul, add, exact *2^-12, round-half-even.
DI float bn_clip(int c, float alpha, float bq) {
    float t = __fmul_rn(alpha, (float)c);
    t = __fadd_rn(t, bq);
    t = t * 0.000244140625f;   // 2^-12, exact scaling
    float v = rintf(t);
    v = fminf(fmaxf(v, -128.f), 127.f);
    return v;
}

// ---------------------------------------------------------------------------
// Pack x: NCHW int32 -> NHWC int8 via smem transpose (coalesced both sides)
// ---------------------------------------------------------------------------
__global__ void pack_x_kernel(const int* __restrict__ x) {
    __shared__ int tile[32][33];
    const int n = blockIdx.z, c0 = blockIdx.y * 32, hw0 = blockIdx.x * 32;
    const int tid = threadIdx.x;
#pragma unroll
    for (int k = 0; k < 4; k++) {
        int e = tid + k * 256;
        int cr = e >> 5, col = e & 31;
        int hw = hw0 + col;
        int v = 0;
        if (hw < HW) v = x[(((n << 10) + c0 + cr) * HW) + hw];
        tile[cr][col] = v;
    }
    __syncthreads();
    const int hwl = tid >> 3, cg = tid & 7;
    const int hw = hw0 + hwl;
    if (hw < HW) {
        char4 p;
        p.x = (char)tile[cg * 4 + 0][hwl];
        p.y = (char)tile[cg * 4 + 1][hwl];
        p.z = (char)tile[cg * 4 + 2][hwl];
        p.w = (char)tile[cg * 4 + 3][hwl];
        *(char4*)(g_x8 + (((size_t)n * HW + hw) << 10) + c0 + cg * 4) = p;
    }
}

// ---------------------------------------------------------------------------
// Weight packing: effective weight = w2 * 2^s  (w2 in {-1,0,1}, s in {0,1,2})
// ---------------------------------------------------------------------------
__global__ void pack_w_kernel(const float* __restrict__ w2,
                              const int* __restrict__ s,
                              int8_t* __restrict__ dst, int total) {
    int i = blockIdx.x * 256 + threadIdx.x;
    if (i < total) {
        int iv = (int)w2[i];
        dst[i] = (int8_t)(iv * (1 << s[i]));
    }
}

// w2_2: [co][ci][kh][kw] -> [co][kh*3+kw][ci]
__global__ void pack_w2_kernel(const float* __restrict__ w2,
                               const int* __restrict__ s) {
    int i = blockIdx.x * 256 + threadIdx.x;
    if (i < CMID * 2304) {
        int co = i / 2304;
        int rem = i - co * 2304;
        int p = rem >> 8, ci = rem & 255;
        int src = (co * 256 + ci) * 9 + p;
        int iv = (int)w2[src];
        g_w2[i] = (int8_t)(iv * (1 << s[src]));
    }
}

// ---------------------------------------------------------------------------
// GEMM config: BM=BN=128, BK=64, 256 threads (8 warps = 2M x 4N),
// each warp: 64x32 via 4x4 mma m16n8k32. smem rows padded to 80B.
// ---------------------------------------------------------------------------
#define LDP   80
#define TILEB (128 * LDP)

DI void frag_compute(const int8_t* cA, const int8_t* cB,
                     int wm, int wn, int g, int tg, int acc[4][4][4]) {
#pragma unroll
    for (int ki = 0; ki < 2; ki++) {
        const int kb = ki * 32 + tg * 4;
        unsigned a[4][4], b[4][2];
#pragma unroll
        for (int i = 0; i < 4; i++) {
            const int8_t* p = cA + (wm + i * 16 + g) * LDP + kb;
            a[i][0] = *(const unsigned*)(p);
            a[i][1] = *(const unsigned*)(p + 8 * LDP);
            a[i][2] = *(const unsigned*)(p + 16);
            a[i][3] = *(const unsigned*)(p + 8 * LDP + 16);
        }
#pragma unroll
        for (int j = 0; j < 4; j++) {
            const int8_t* p = cB + (wn + j * 8 + g) * LDP + kb;
            b[j][0] = *(const unsigned*)(p);
            b[j][1] = *(const unsigned*)(p + 16);
        }
#pragma unroll
        for (int i = 0; i < 4; i++)
#pragma unroll
            for (int j = 0; j < 4; j++)
                mma8(acc[i][j], a[i], b[j]);
    }
}

// K: reduction size; FINAL: gemm3 (identity add + float out) vs gemm1 (int8 out)
template <int K, bool FINAL>
__global__ __launch_bounds__(256, 1)
void gemm_kernel(const float* __restrict__ alpha, const float* __restrict__ beta,
                 const int* __restrict__ q,
                 const int* __restrict__ Xid, float* __restrict__ Fout) {
    __shared__ __align__(16) int8_t smem[4 * TILEB];
    int8_t* sA = smem;
    int8_t* sB = smem + 2 * TILEB;

    const int8_t* __restrict__ A = FINAL ? g_w3 : g_w1;
    const int8_t* __restrict__ B = FINAL ? g_y2 : g_x8;

    const int tid = threadIdx.x, lane = tid & 31, warp = tid >> 5;
    const int g = lane >> 2, tg = lane & 3;
    const int wm = (warp >> 2) * 64, wn = (warp & 3) * 32;
    const int mBase = blockIdx.y * 128, sBase = blockIdx.x * 128;

    int acc[4][4][4];
#pragma unroll
    for (int i = 0; i < 4; i++)
#pragma unroll
        for (int j = 0; j < 4; j++)
#pragma unroll
            for (int k = 0; k < 4; k++) acc[i][j][k] = 0;

    const int row = tid >> 1, off = (tid & 1) * 32;
    const int8_t* gA = A + (size_t)(mBase + row) * K + off;
    const int8_t* gB = B + (size_t)(sBase + row) * K + off;
    int8_t* sAw = sA + row * LDP + off;
    int8_t* sBw = sB + row * LDP + off;

    constexpr int KT = K / 64;
    // prologue: fill buffer 0
    {
        int4 a0 = *(const int4*)(gA);
        int4 a1 = *(const int4*)(gA + 16);
        int4 b0 = *(const int4*)(gB);
        int4 b1 = *(const int4*)(gB + 16);
        *(int4*)(sAw) = a0; *(int4*)(sAw + 16) = a1;
        *(int4*)(sBw) = b0; *(int4*)(sBw + 16) = b1;
    }

#pragma unroll 1
    for (int kt = 0; kt < KT; kt++) {
        __syncthreads();
        const int buf = kt & 1;
        int4 na0, na1, nb0, nb1;
        const bool more = (kt + 1 < KT);
        if (more) {
            const int8_t* pa = gA + (kt + 1) * 64;
            const int8_t* pb = gB + (kt + 1) * 64;
            na0 = *(const int4*)pa; na1 = *(const int4*)(pa + 16);
            nb0 = *(const int4*)pb; nb1 = *(const int4*)(pb + 16);
        }
        frag_compute(sA + buf * TILEB, sB + buf * TILEB, wm, wn, g, tg, acc);
        if (more) {
            int8_t* wA = sAw + (buf ^ 1) * TILEB;
            int8_t* wB = sBw + (buf ^ 1) * TILEB;
            *(int4*)wA = na0; *(int4*)(wA + 16) = na1;
            *(int4*)wB = nb0; *(int4*)(wB + 16) = nb1;
        }
    }
    __syncthreads();

    if (!FINAL) {
        // epilogue: BN + clip + relu -> int8, stage in smem, coalesced store
        int8_t* stg = smem;  // [128 spatial][128 co]
#pragma unroll
        for (int i = 0; i < 4; i++) {
            const int co0 = wm + i * 16 + g, co1 = co0 + 8;
            const float al0 = alpha[mBase + co0], al1 = alpha[mBase + co1];
            const float bq0 = beta[mBase + co0] * (float)(1 << (q[mBase + co0] + 12));
            const float bq1 = beta[mBase + co1] * (float)(1 << (q[mBase + co1] + 12));
#pragma unroll
            for (int j = 0; j < 4; j++) {
                const int s0 = wn + j * 8 + tg * 2;
                stg[(s0)     * 128 + co0] = (int8_t)fmaxf(bn_clip(acc[i][j][0], al0, bq0), 0.f);
                stg[(s0 + 1) * 128 + co0] = (int8_t)fmaxf(bn_clip(acc[i][j][1], al0, bq0), 0.f);
                stg[(s0)     * 128 + co1] = (int8_t)fmaxf(bn_clip(acc[i][j][2], al1, bq1), 0.f);
                stg[(s0 + 1) * 128 + co1] = (int8_t)fmaxf(bn_clip(acc[i][j][3], al1, bq1), 0.f);
            }
        }
        __syncthreads();
        const int rs = tid >> 1, o64 = (tid & 1) * 64;
        int8_t* dst = g_y1 + (size_t)(sBase + rs) * 256 + mBase + o64;
        const int8_t* src = stg + rs * 128 + o64;
#pragma unroll
        for (int k = 0; k < 4; k++)
            *(int4*)(dst + k * 16) = *(const int4*)(src + k * 16);
    } else {
        // epilogue: BN + clip, + identity, clip, relu -> float, in 2 halves
        float* stg = (float*)smem;  // [128 co][64 spatial]
#pragma unroll 1
        for (int h = 0; h < 2; h++) {
            if ((wn >= 64) == (h == 1)) {
                const int wnl = wn & 63;
#pragma unroll
                for (int i = 0; i < 4; i++) {
                    const int co0 = wm + i * 16 + g, co1 = co0 + 8;
                    const float al0 = alpha[mBase + co0], al1 = alpha[mBase + co1];
                    const float bq0 = beta[mBase + co0] * (float)(1 << (q[mBase + co0] + 12));
                    const float bq1 = beta[mBase + co1] * (float)(1 << (q[mBase + co1] + 12));
#pragma unroll
                    for (int j = 0; j < 4; j++) {
                        const int sl = wnl + j * 8 + tg * 2;
                        stg[co0 * 64 + sl]     = bn_clip(acc[i][j][0], al0, bq0);
                        stg[co0 * 64 + sl + 1] = bn_clip(acc[i][j][1], al0, bq0);
                        stg[co1 * 64 + sl]     = bn_clip(acc[i][j][2], al1, bq1);
                        stg[co1 * 64 + sl + 1] = bn_clip(acc[i][j][3], al1, bq1);
                    }
                }
            }
            __syncthreads();
            for (int e = tid; e < 128 * 64; e += 256) {
                const int co_l = e >> 6, sl = e & 63;
                const int sg = sBase + h * 64 + sl;
                const int n = sg / HW, hw = sg - n * HW;
                const int co = mBase + co_l;
                const int idx = ((n << 10) + co) * HW + hw;
                float v = stg[e] + (float)Xid[idx];
                v = fminf(fmaxf(v, -128.f), 127.f);
                v = fmaxf(v, 0.f);
                Fout[idx] = v;
            }
            __syncthreads();
        }
    }
}

// ---------------------------------------------------------------------------
// 3x3 conv: im2col-style GEMM with smem gather. Block = (co 128) x (4x32 tile)
// ---------------------------------------------------------------------------
__global__ __launch_bounds__(256, 1)
void conv2_kernel(const float* __restrict__ alpha, const float* __restrict__ beta,
                  const int* __restrict__ q) {
    __shared__ __align__(16) int8_t smem[4 * TILEB];
    int8_t* sA = smem;
    int8_t* sB = smem + 2 * TILEB;

    const int tid = threadIdx.x, lane = tid & 31, warp = tid >> 5;
    const int g = lane >> 2, tg = lane & 3;
    const int wm = (warp >> 2) * 64, wn = (warp & 3) * 32;
    const int mBase = blockIdx.x * 128;
    const int h0 = blockIdx.y * 4;
    const int n = blockIdx.z;

    int acc[4][4][4];
#pragma unroll
    for (int i = 0; i < 4; i++)
#pragma unroll
        for (int j = 0; j < 4; j++)
#pragma unroll
            for (int k = 0; k < 4; k++) acc[i][j][k] = 0;

    const int row = tid >> 1, off = (tid & 1) * 32;
    const int r = row >> 5, c = row & 31;   // spatial decomposition of B row
    const int8_t* gA = g_w2 + (size_t)(mBase + row) * 2304 + off;
    int8_t* sAw = sA + row * LDP + off;
    int8_t* sBw = sB + row * LDP + off;

    // B gather for step kt
    auto loadB = [&](int kt, int4& b0, int4& b1) {
        const int kh = kt / 12;
        const int rem = kt - kh * 12;
        const int kw = rem >> 2, ck = rem & 3;
        const int ih = h0 + r + kh - 1;
        const int iw = c + kw - 1;
        b0 = make_int4(0, 0, 0, 0);
        b1 = make_int4(0, 0, 0, 0);
        if ((unsigned)ih < 28u && (unsigned)iw < 28u) {
            const int8_t* p = g_y1 + (((size_t)n * HW + ih * 28 + iw) << 8) + ck * 64 + off;
            b0 = *(const int4*)p;
            b1 = *(const int4*)(p + 16);
        }
    };

    // prologue
    {
        int4 a0 = *(const int4*)(gA);
        int4 a1 = *(const int4*)(gA + 16);
        int4 b0, b1;
        loadB(0, b0, b1);
        *(int4*)(sAw) = a0; *(int4*)(sAw + 16) = a1;
        *(int4*)(sBw) = b0; *(int4*)(sBw + 16) = b1;
    }

    const int KT = 36;
#pragma unroll 1
    for (int kt = 0; kt < KT; kt++) {
        __syncthreads();
        const int buf = kt & 1;
        int4 na0, na1, nb0, nb1;
        const bool more = (kt + 1 < KT);
        if (more) {
            const int8_t* pa = gA + (kt + 1) * 64;
            na0 = *(const int4*)pa; na1 = *(const int4*)(pa + 16);
            loadB(kt + 1, nb0, nb1);
        }
        frag_compute(sA + buf * TILEB, sB + buf * TILEB, wm, wn, g, tg, acc);
        if (more) {
            int8_t* wA = sAw + (buf ^ 1) * TILEB;
            int8_t* wB = sBw + (buf ^ 1) * TILEB;
            *(int4*)wA = na0; *(int4*)(wA + 16) = na1;
            *(int4*)wB = nb0; *(int4*)(wB + 16) = nb1;
        }
    }
    __syncthreads();

    // epilogue: BN + clip + relu -> int8 stage -> coalesced store (w<28 only)
    int8_t* stg = smem;
#pragma unroll
    for (int i = 0; i < 4; i++) {
        const int co0 = wm + i * 16 + g, co1 = co0 + 8;
        const float al0 = alpha[mBase + co0], al1 = alpha[mBase + co1];
        const float bq0 = beta[mBase + co0] * (float)(1 << (q[mBase + co0] + 12));
        const float bq1 = beta[mBase + co1] * (float)(1 << (q[mBase + co1] + 12));
#pragma unroll
        for (int j = 0; j < 4; j++) {
            const int s0 = wn + j * 8 + tg * 2;
            stg[(s0)     * 128 + co0] = (int8_t)fmaxf(bn_clip(acc[i][j][0], al0, bq0), 0.f);
            stg[(s0 + 1) * 128 + co0] = (int8_t)fmaxf(bn_clip(acc[i][j][1], al0, bq0), 0.f);
            stg[(s0)     * 128 + co1] = (int8_t)fmaxf(bn_clip(acc[i][j][2], al1, bq1), 0.f);
            stg[(s0 + 1) * 128 + co1] = (int8_t)fmaxf(bn_clip(acc[i][j][3], al1, bq1), 0.f);
        }
    }
    __syncthreads();
    const int rs = tid >> 1, o64 = (tid & 1) * 64;
    const int rr = rs >> 5, cc = rs & 31;
    if (cc < 28) {
        int8_t* dst = g_y2 + (((size_t)n * HW + (h0 + rr) * 28 + cc) << 8) + mBase + o64;
        const int8_t* src = stg + rs * 128 + o64;
#pragma unroll
        for (int k = 0; k < 4; k++)
            *(int4*)(dst + k * 16) = *(const int4*)(src + k * 16);
    }
}

// ---------------------------------------------------------------------------
extern "C" void kernel_launch(void* const* d_in, const int* in_sizes, int n_in,
                              void* d_out, int out_size) {
    const int*   x      = (const int*)d_in[0];
    const float* w2_1   = (const float*)d_in[1];
    const int*   s1     = (const int*)d_in[2];
    const float* w2_2   = (const float*)d_in[3];
    const int*   s2     = (const int*)d_in[4];
    const float* w2_3   = (const float*)d_in[5];
    const int*   s3     = (const int*)d_in[6];
    const float* alpha1 = (const float*)d_in[7];
    const float* beta1  = (const float*)d_in[8];
    const int*   q1     = (const int*)d_in[9];
    const float* alpha2 = (const float*)d_in[10];
    const float* beta2  = (const float*)d_in[11];
    const int*   q2     = (const int*)d_in[12];
    const float* alpha3 = (const float*)d_in[13];
    const float* beta3  = (const float*)d_in[14];
    const int*   q3     = (const int*)d_in[15];
    float* out = (float*)d_out;

    // prep
    pack_x_kernel<<<dim3(25, 32, 16), 256>>>(x);
    {
        int8_t* w1p; cudaGetSymbolAddress((void**)&w1p, g_w1);
        int8_t* w3p; cudaGetSymbolAddress((void**)&w3p, g_w3);
        pack_w_kernel<<<1024, 256>>>(w2_1, s1, w1p, CMID * CIN);
        pack_w2_kernel<<<2304, 256>>>(w2_2, s2);
        pack_w_kernel<<<1024, 256>>>(w2_3, s3, w3p, COUT * CMID);
    }

    // conv1: [256 x 12544] = W1[256x1024] * X[1024x12544]
    gemm_kernel<1024, false><<<dim3(98, 2), 256>>>(alpha1, beta1, q1, nullptr, nullptr);
    // conv2: 3x3, im2col K=2304
    conv2_kernel<<<dim3(2, 7, 16), 256>>>(alpha2, beta2, q2);
    // conv3: [1024 x 12544] = W3[1024x256] * Y2[256x12544], + identity
    gemm_kernel<256, true><<<dim3(98, 8), 256>>>(alpha3, beta3, q3, x, out);
}

// round 5
// speedup vs baseline: 1.1890x; 1.1890x over previous
#include <cuda_runtime.h>
#include <cuda_bf16.h>
#include <stdint.h>

// ---------------------------------------------------------------------------
// Quantized bottleneck: all convs are exact int8 GEMMs (weights in {-4..4},
// activations in [-128,127] after each BN/clip/relu). mma.sync.m16n8k32.s8
// with ldmatrix fragment loads + cp.async 3-stage pipeline.
// Float BN epilogue replicated exactly (rintf = round-half-even).
// ---------------------------------------------------------------------------

#define NIMG   16
#define HW     784           // 28*28
#define NS     12544         // NIMG*HW
#define CIN    1024
#define CMID   256
#define COUT   1024

__device__ int8_t g_x8[NS * CIN];          // x packed NHWC int8
__device__ int8_t g_w1[CMID * CIN];        // [co][ci]
__device__ int8_t g_w2[CMID * 2304];       // [co][kh][kw][ci]
__device__ int8_t g_w3[COUT * CMID];       // [co][ci]
__device__ int8_t g_y1[NS * CMID];         // NHWC int8
__device__ int8_t g_y2[NS * CMID];         // NHWC int8

#define DI __device__ __forceinline__

DI void mma8(int* d, const unsigned* a, const unsigned* b) {
    asm volatile(
        "mma.sync.aligned.m16n8k32.row.col.s32.s8.s8.s32 "
        "{%0,%1,%2,%3}, {%4,%5,%6,%7}, {%8,%9}, {%0,%1,%2,%3};\n"
        : "+r"(d[0]), "+r"(d[1]), "+r"(d[2]), "+r"(d[3])
        : "r"(a[0]), "r"(a[1]), "r"(a[2]), "r"(a[3]),
          "r"(b[0]), "r"(b[1]));
}

DI void ldsm4(unsigned& r0, unsigned& r1, unsigned& r2, unsigned& r3, uint32_t addr) {
    asm volatile("ldmatrix.sync.aligned.m8n8.x4.shared.b16 {%0,%1,%2,%3}, [%4];\n"
        : "=r"(r0), "=r"(r1), "=r"(r2), "=r"(r3) : "r"(addr));
}

DI void cp16(uint32_t saddr, const void* gptr, bool pred) {
    int sz = pred ? 16 : 0;
    asm volatile("cp.async.cg.shared.global [%0], [%1], 16, %2;\n"
        :: "r"(saddr), "l"(gptr), "r"(sz));
}
DI void cp_commit() { asm volatile("cp.async.commit_group;\n"); }
template <int N> DI void cp_wait() { asm volatile("cp.async.wait_group %0;\n" :: "n"(N)); }

// BN: round((alpha*c + beta*2^(q+12)) * 2^-12), clip to [-128,127].
DI float bn_clip(int c, float alpha, float bq) {
    float t = __fmul_rn(alpha, (float)c);
    t = __fadd_rn(t, bq);
    t = t * 0.000244140625f;   // 2^-12 exact
    float v = rintf(t);
    v = fminf(fmaxf(v, -128.f), 127.f);
    return v;
}

// ---------------------------------------------------------------------------
// Pack x: NCHW int32 -> NHWC int8 via smem transpose
// ---------------------------------------------------------------------------
__global__ void pack_x_kernel(const int* __restrict__ x) {
    __shared__ int tile[32][33];
    const int n = blockIdx.z, c0 = blockIdx.y * 32, hw0 = blockIdx.x * 32;
    const int tid = threadIdx.x;
#pragma unroll
    for (int k = 0; k < 4; k++) {
        int e = tid + k * 256;
        int cr = e >> 5, col = e & 31;
        int hw = hw0 + col;
        int v = 0;
        if (hw < HW) v = x[(((n << 10) + c0 + cr) * HW) + hw];
        tile[cr][col] = v;
    }
    __syncthreads();
    const int hwl = tid >> 3, cg = tid & 7;
    const int hw = hw0 + hwl;
    if (hw < HW) {
        char4 p;
        p.x = (char)tile[cg * 4 + 0][hwl];
        p.y = (char)tile[cg * 4 + 1][hwl];
        p.z = (char)tile[cg * 4 + 2][hwl];
        p.w = (char)tile[cg * 4 + 3][hwl];
        *(char4*)(g_x8 + (((size_t)n * HW + hw) << 10) + c0 + cg * 4) = p;
    }
}

__global__ void pack_w_kernel(const float* __restrict__ w2,
                              const int* __restrict__ s,
                              int8_t* __restrict__ dst, int total) {
    int i = blockIdx.x * 256 + threadIdx.x;
    if (i < total) {
        int iv = (int)w2[i];
        dst[i] = (int8_t)(iv * (1 << s[i]));
    }
}

// w2_2: [co][ci][kh][kw] -> [co][kh*3+kw][ci]
__global__ void pack_w2_kernel(const float* __restrict__ w2,
                               const int* __restrict__ s) {
    int i = blockIdx.x * 256 + threadIdx.x;
    if (i < CMID * 2304) {
        int co = i / 2304;
        int rem = i - co * 2304;
        int p = rem >> 8, ci = rem & 255;
        int src = (co * 256 + ci) * 9 + p;
        int iv = (int)w2[src];
        g_w2[i] = (int8_t)(iv * (1 << s[src]));
    }
}

// ---------------------------------------------------------------------------
// GEMM core: BM=BN=128, BK=64, 256 threads (8 warps = 2M x 4N), warp 64x32.
// smem: swizzled 64B rows, blk' = blk ^ ((row>>1)&3). 3-stage cp.async.
// ---------------------------------------------------------------------------
#define STAGES      3
#define TILE_BYTES  (128 * 64)             // 8 KB per matrix per stage
#define STAGE_BYTES (2 * TILE_BYTES)       // 16 KB
#define SMEM_BYTES  (STAGES * STAGE_BYTES) // 48 KB

#define SWB(row, blk) (((blk) ^ (((row) >> 1) & 3)) << 4)

// fragment compute for one 64-K stage
#define COMPUTE_STAGE(aS, bS)                                                  \
    do {                                                                       \
        _Pragma("unroll")                                                      \
        for (int ki = 0; ki < 2; ki++) {                                       \
            unsigned a[4][4], b[4][2];                                         \
            _Pragma("unroll")                                                  \
            for (int i = 0; i < 4; i++)                                        \
                ldsm4(a[i][0], a[i][1], a[i][2], a[i][3],                      \
                      (aS) + (unsigned)((rowA + i * 16) * 64) +                \
                          (unsigned)SWB(rowA, ki * 2 + blkA));                 \
            _Pragma("unroll")                                                  \
            for (int jp = 0; jp < 2; jp++)                                     \
                ldsm4(b[2 * jp][0], b[2 * jp][1], b[2 * jp + 1][0],            \
                      b[2 * jp + 1][1],                                        \
                      (bS) + (unsigned)((rowB + jp * 16) * 64) +               \
                          (unsigned)SWB(rowB, ki * 2 + blkB));                 \
            _Pragma("unroll")                                                  \
            for (int i = 0; i < 4; i++)                                        \
                _Pragma("unroll")                                              \
                for (int j = 0; j < 4; j++) mma8(acc[i][j], a[i], b[j]);       \
        }                                                                      \
    } while (0)

template <int K, bool FINAL>
__global__ __launch_bounds__(256, 2)
void gemm_kernel(const float* __restrict__ alpha, const float* __restrict__ beta,
                 const int* __restrict__ q,
                 const int* __restrict__ Xid, float* __restrict__ Fout) {
    __shared__ __align__(16) int8_t smem[SMEM_BYTES];
    const uint32_t sbase = (uint32_t)__cvta_generic_to_shared(smem);

    const int8_t* __restrict__ A = FINAL ? g_w3 : g_w1;
    const int8_t* __restrict__ B = FINAL ? g_y2 : g_x8;

    const int tid = threadIdx.x, lane = tid & 31, warp = tid >> 5;
    const int g = lane >> 2, tg = lane & 3;
    const int wm = (warp >> 2) * 64, wn = (warp & 3) * 32;
    const int mBase = blockIdx.y * 128, sBase = blockIdx.x * 128;

    // ldmatrix lane geometry
    const int m8 = lane >> 3, r8 = lane & 7;
    const int rowA = wm + ((m8 & 1) << 3) + r8;
    const int blkA = m8 >> 1;
    const int rowB = wn + ((m8 >> 1) << 3) + r8;
    const int blkB = m8 & 1;

    int acc[4][4][4];
#pragma unroll
    for (int i = 0; i < 4; i++)
#pragma unroll
        for (int j = 0; j < 4; j++)
#pragma unroll
            for (int k = 0; k < 4; k++) acc[i][j][k] = 0;

    // per-thread cp.async geometry: 2 chunks of 16B for A, 2 for B
    auto issue = [&](int kt, int stage) {
        const uint32_t sa = sbase + stage * STAGE_BYTES;
        const uint32_t sb = sa + TILE_BYTES;
#pragma unroll
        for (int u = 0; u < 2; u++) {
            const int c = tid + u * 256;
            const int row = c >> 2, blk = c & 3;
            const uint32_t so = (uint32_t)(row * 64) + (uint32_t)SWB(row, blk);
            cp16(sa + so, A + (size_t)(mBase + row) * K + kt * 64 + blk * 16, true);
            cp16(sb + so, B + (size_t)(sBase + row) * K + kt * 64 + blk * 16, true);
        }
    };

    constexpr int KT = K / 64;
#pragma unroll
    for (int s = 0; s < STAGES - 1; s++) { issue(s, s); cp_commit(); }

#pragma unroll 1
    for (int kt = 0; kt < KT; kt++) {
        cp_wait<STAGES - 2>();
        __syncthreads();
        if (kt + STAGES - 1 < KT) issue(kt + STAGES - 1, (kt + STAGES - 1) % STAGES);
        cp_commit();
        const uint32_t aS = sbase + (kt % STAGES) * STAGE_BYTES;
        COMPUTE_STAGE(aS, aS + TILE_BYTES);
    }
    cp_wait<0>();
    __syncthreads();

    if (!FINAL) {
        // BN + clip + relu -> int8, stage in smem, coalesced store
        int8_t* stg = smem;  // [128 spatial][128 co]
#pragma unroll
        for (int i = 0; i < 4; i++) {
            const int co0 = wm + i * 16 + g, co1 = co0 + 8;
            const float al0 = alpha[mBase + co0], al1 = alpha[mBase + co1];
            const float bq0 = beta[mBase + co0] * (float)(1 << (q[mBase + co0] + 12));
            const float bq1 = beta[mBase + co1] * (float)(1 << (q[mBase + co1] + 12));
#pragma unroll
            for (int j = 0; j < 4; j++) {
                const int s0 = wn + j * 8 + tg * 2;
                stg[(s0)     * 128 + co0] = (int8_t)fmaxf(bn_clip(acc[i][j][0], al0, bq0), 0.f);
                stg[(s0 + 1) * 128 + co0] = (int8_t)fmaxf(bn_clip(acc[i][j][1], al0, bq0), 0.f);
                stg[(s0)     * 128 + co1] = (int8_t)fmaxf(bn_clip(acc[i][j][2], al1, bq1), 0.f);
                stg[(s0 + 1) * 128 + co1] = (int8_t)fmaxf(bn_clip(acc[i][j][3], al1, bq1), 0.f);
            }
        }
        __syncthreads();
        const int rs = tid >> 1, o64 = (tid & 1) * 64;
        int8_t* dst = g_y1 + (size_t)(sBase + rs) * 256 + mBase + o64;
        const int8_t* src = stg + rs * 128 + o64;
#pragma unroll
        for (int k = 0; k < 4; k++)
            *(int4*)(dst + k * 16) = *(const int4*)(src + k * 16);
    } else {
        // BN + clip, + identity, clip, relu -> float, two 64-spatial halves
        float* stg = (float*)smem;  // [128 co][64 spatial]
#pragma unroll 1
        for (int h = 0; h < 2; h++) {
            if ((wn >= 64) == (h == 1)) {
                const int wnl = wn & 63;
#pragma unroll
                for (int i = 0; i < 4; i++) {
                    const int co0 = wm + i * 16 + g, co1 = co0 + 8;
                    const float al0 = alpha[mBase + co0], al1 = alpha[mBase + co1];
                    const float bq0 = beta[mBase + co0] * (float)(1 << (q[mBase + co0] + 12));
                    const float bq1 = beta[mBase + co1] * (float)(1 << (q[mBase + co1] + 12));
#pragma unroll
                    for (int j = 0; j < 4; j++) {
                        const int sl = wnl + j * 8 + tg * 2;
                        stg[co0 * 64 + sl]     = bn_clip(acc[i][j][0], al0, bq0);
                        stg[co0 * 64 + sl + 1] = bn_clip(acc[i][j][1], al0, bq0);
                        stg[co1 * 64 + sl]     = bn_clip(acc[i][j][2], al1, bq1);
                        stg[co1 * 64 + sl + 1] = bn_clip(acc[i][j][3], al1, bq1);
                    }
                }
            }
            __syncthreads();
            for (int e = tid; e < 128 * 64; e += 256) {
                const int co_l = e >> 6, sl = e & 63;
                const int sg = sBase + h * 64 + sl;
                const int n = sg / HW, hw = sg - n * HW;
                const int co = mBase + co_l;
                const int idx = ((n << 10) + co) * HW + hw;
                float v = stg[e] + (float)Xid[idx];
                v = fminf(fmaxf(v, -128.f), 127.f);
                v = fmaxf(v, 0.f);
                Fout[idx] = v;
            }
            __syncthreads();
        }
    }
}

// ---------------------------------------------------------------------------
// 3x3 conv: im2col GEMM, gather B with zero-fill cp.async for halo.
// ---------------------------------------------------------------------------
__global__ __launch_bounds__(256, 2)
void conv2_kernel(const float* __restrict__ alpha, const float* __restrict__ beta,
                  const int* __restrict__ q) {
    __shared__ __align__(16) int8_t smem[SMEM_BYTES];
    const uint32_t sbase = (uint32_t)__cvta_generic_to_shared(smem);

    const int tid = threadIdx.x, lane = tid & 31, warp = tid >> 5;
    const int g = lane >> 2, tg = lane & 3;
    const int wm = (warp >> 2) * 64, wn = (warp & 3) * 32;
    const int mBase = blockIdx.x * 128;
    const int h0 = blockIdx.y * 4;
    const int n = blockIdx.z;

    const int m8 = lane >> 3, r8 = lane & 7;
    const int rowA = wm + ((m8 & 1) << 3) + r8;
    const int blkA = m8 >> 1;
    const int rowB = wn + ((m8 >> 1) << 3) + r8;
    const int blkB = m8 & 1;

    int acc[4][4][4];
#pragma unroll
    for (int i = 0; i < 4; i++)
#pragma unroll
        for (int j = 0; j < 4; j++)
#pragma unroll
            for (int k = 0; k < 4; k++) acc[i][j][k] = 0;

    auto issue = [&](int kt, int stage) {
        const uint32_t sa = sbase + stage * STAGE_BYTES;
        const uint32_t sb = sa + TILE_BYTES;
        const int kh = kt / 12;
        const int rem = kt - kh * 12;
        const int kw = rem >> 2, ck = rem & 3;
#pragma unroll
        for (int u = 0; u < 2; u++) {
            const int c = tid + u * 256;
            const int row = c >> 2, blk = c & 3;
            const uint32_t so = (uint32_t)(row * 64) + (uint32_t)SWB(row, blk);
            cp16(sa + so, g_w2 + (size_t)(mBase + row) * 2304 + kt * 64 + blk * 16, true);
            const int rr = row >> 5, cc = row & 31;
            const int ih = h0 + rr + kh - 1;
            const int iw = cc + kw - 1;
            const bool ok = ((unsigned)ih < 28u) && ((unsigned)iw < 28u);
            const int8_t* src = ok
                ? g_y1 + (((size_t)n * HW + ih * 28 + iw) << 8) + ck * 64 + blk * 16
                : g_y1;
            cp16(sb + so, src, ok);
        }
    };

    const int KT = 36;
#pragma unroll
    for (int s = 0; s < STAGES - 1; s++) { issue(s, s); cp_commit(); }

#pragma unroll 1
    for (int kt = 0; kt < KT; kt++) {
        cp_wait<STAGES - 2>();
        __syncthreads();
        if (kt + STAGES - 1 < KT) issue(kt + STAGES - 1, (kt + STAGES - 1) % STAGES);
        cp_commit();
        const uint32_t aS = sbase + (kt % STAGES) * STAGE_BYTES;
        COMPUTE_STAGE(aS, aS + TILE_BYTES);
    }
    cp_wait<0>();
    __syncthreads();

    // BN + clip + relu -> int8 stage -> coalesced store (w<28 only)
    int8_t* stg = smem;
#pragma unroll
    for (int i = 0; i < 4; i++) {
        const int co0 = wm + i * 16 + g, co1 = co0 + 8;
        const float al0 = alpha[mBase + co0], al1 = alpha[mBase + co1];
        const float bq0 = beta[mBase + co0] * (float)(1 << (q[mBase + co0] + 12));
        const float bq1 = beta[mBase + co1] * (float)(1 << (q[mBase + co1] + 12));
#pragma unroll
        for (int j = 0; j < 4; j++) {
            const int s0 = wn + j * 8 + tg * 2;
            stg[(s0)     * 128 + co0] = (int8_t)fmaxf(bn_clip(acc[i][j][0], al0, bq0), 0.f);
            stg[(s0 + 1) * 128 + co0] = (int8_t)fmaxf(bn_clip(acc[i][j][1], al0, bq0), 0.f);
            stg[(s0)     * 128 + co1] = (int8_t)fmaxf(bn_clip(acc[i][j][2], al1, bq1), 0.f);
            stg[(s0 + 1) * 128 + co1] = (int8_t)fmaxf(bn_clip(acc[i][j][3], al1, bq1), 0.f);
        }
    }
    __syncthreads();
    const int rs = tid >> 1, o64 = (tid & 1) * 64;
    const int rr = rs >> 5, cc = rs & 31;
    if (cc < 28) {
        int8_t* dst = g_y2 + (((size_t)n * HW + (h0 + rr) * 28 + cc) << 8) + mBase + o64;
        const int8_t* src = stg + rs * 128 + o64;
#pragma unroll
        for (int k = 0; k < 4; k++)
            *(int4*)(dst + k * 16) = *(const int4*)(src + k * 16);
    }
}

// ---------------------------------------------------------------------------
extern "C" void kernel_launch(void* const* d_in, const int* in_sizes, int n_in,
                              void* d_out, int out_size) {
    const int*   x      = (const int*)d_in[0];
    const float* w2_1   = (const float*)d_in[1];
    const int*   s1     = (const int*)d_in[2];
    const float* w2_2   = (const float*)d_in[3];
    const int*   s2     = (const int*)d_in[4];
    const float* w2_3   = (const float*)d_in[5];
    const int*   s3     = (const int*)d_in[6];
    const float* alpha1 = (const float*)d_in[7];
    const float* beta1  = (const float*)d_in[8];
    const int*   q1     = (const int*)d_in[9];
    const float* alpha2 = (const float*)d_in[10];
    const float* beta2  = (const float*)d_in[11];
    const int*   q2     = (const int*)d_in[12];
    const float* alpha3 = (const float*)d_in[13];
    const float* beta3  = (const float*)d_in[14];
    const int*   q3     = (const int*)d_in[15];
    float* out = (float*)d_out;

    pack_x_kernel<<<dim3(25, 32, 16), 256>>>(x);
    {
        int8_t* w1p; cudaGetSymbolAddress((void**)&w1p, g_w1);
        int8_t* w3p; cudaGetSymbolAddress((void**)&w3p, g_w3);
        pack_w_kernel<<<1024, 256>>>(w2_1, s1, w1p, CMID * CIN);
        pack_w2_kernel<<<2304, 256>>>(w2_2, s2);
        pack_w_kernel<<<1024, 256>>>(w2_3, s3, w3p, COUT * CMID);
    }

    // conv1: [256 x 12544] = W1[256x1024] * X[1024x12544]
    gemm_kernel<1024, false><<<dim3(98, 2), 256>>>(alpha1, beta1, q1, nullptr, nullptr);
    // conv2: 3x3, im2col K=2304
    conv2_kernel<<<dim3(2, 7, 16), 256>>>(alpha2, beta2, q2);
    // conv3: [1024 x 12544] = W3[1024x256] * Y2[256x12544], + identity
    gemm_kernel<256, true><<<dim3(98, 8), 256>>>(alpha3, beta3, q3, x, out);
}